// round 8
// baseline (speedup 1.0000x reference)
#include <cuda_runtime.h>
#include <math.h>

// Shapes (fixed):
//   root_rvel : (256, 1024, 1, 1)
//   local_pos : (256, 1025, 24, 3)
//   local_rot : (256, 1025, 24, 6)
//   root_vel  : (256, 1024, 1, 2)
// Output: concat(flatten(global_pos), flatten(global_rot))

#define NB   256
#define T    1024
#define TP1  1025
#define J    24
#define TOT2 (NB * TP1 * J)           // 6,297,600
#define POS_ELEMS (NB * TP1 * J * 3)  // 18,892,800

__device__ float2 g_rot[NB * TP1];  // (ch, sh) half-angle quat (w, y)
__device__ float2 g_pos[NB * TP1];  // integrated (px, pz)

// Plain (non-contracted) fp32 ops to match XLA's mul/add/sub/div exactly.
__device__ __forceinline__ float fM(float a, float b) { return __fmul_rn(a, b); }
__device__ __forceinline__ float fA(float a, float b) { return __fadd_rn(a, b); }
__device__ __forceinline__ float fS(float a, float b) { return __fsub_rn(a, b); }
__device__ __forceinline__ float fD(float a, float b) { return __fdiv_rn(a, b); }

// _axis_angle_to_quat for aa = (0, r, 0): exact replica of reference arithmetic.
// fp64 trig rounded to fp32 == correctly-rounded == glibc sinf/cosf (CPU ref).
__device__ __forceinline__ void half_cs(float r, float& ch, float& sh) {
    float r2 = __fmul_rn(r, r);
    float an = __fsqrt_rn(r2);
    float half = __fmul_rn(0.5f, an);
    ch = (float)cos((double)half);
    if (an < 1e-6f) {
        float k = __fsub_rn(0.5f, __fdiv_rn(__fmul_rn(an, an), 48.0f));
        sh = __fmul_rn(r, k);
    } else {
        float s32 = (float)sin((double)half);
        float k = __fdiv_rn(s32, an);
        sh = __fmul_rn(r, k);
    }
}

// ---------------------------------------------------------------------------
// XLA ReduceWindowRewriter(base_length=16) cumsum order for length 1024:
//   level A: 64 tiles x 16, sequential L->R scan within tile (init 0)
//   totals u[64] -> recursive: level B: 4 tiles x 16, sequential within tile
//     totals w[4]  -> naive sequential scan (4 <= 16), exclusive by shift
//     scan_u[a] = fl(w_excl[a/16] + mB[a])
//   offsets[a] = scan_u[a-1] (exclusive by shift; 0 for a=0)
//   final[i] = fl(offsets[i/16] + innA[i])
// All adds __fadd_rn, exclusive values taken bit-directly (no re-subtraction).
// ---------------------------------------------------------------------------
__device__ __forceinline__ void rwr16_scan(
    int t, const float* __restrict__ x, float* __restrict__ out,
    float* __restrict__ inn, float* __restrict__ u,
    float* __restrict__ m, float* __restrict__ w)
{
    __syncthreads();   // x fully written
    if (t < 64) {
        float acc = 0.0f;
#pragma unroll
        for (int j = 0; j < 16; j++) {
            acc = __fadd_rn(acc, x[t * 16 + j]);
            inn[t * 16 + j] = acc;
        }
        u[t] = acc;
    }
    __syncthreads();
    if (t < 4) {
        float acc = 0.0f;
#pragma unroll
        for (int j = 0; j < 16; j++) {
            acc = __fadd_rn(acc, u[t * 16 + j]);
            m[t * 16 + j] = acc;
        }
        w[t] = acc;
    }
    __syncthreads();
    if (t == 0) {
        float acc = 0.0f;
#pragma unroll
        for (int c = 0; c < 4; c++) {      // exclusive prefix of w, direct bits
            float p = acc;
            acc = __fadd_rn(acc, w[c]);
            w[c] = p;
        }
    }
    __syncthreads();
    {
        int a = t >> 4;                    // tile index at level A
        float off;
        if (a == 0) {
            off = 0.0f;
        } else {
            int b = a - 1;
            off = __fadd_rn(w[b >> 4], m[b]);   // scan_u[a-1]
        }
        out[t] = __fadd_rn(off, inn[t]);
    }
    __syncthreads();   // out readable by neighbors
}

// ---------------------------------------------------------------------------
// Phase 1: per-batch scans (one 1024-thread block per batch).
// ---------------------------------------------------------------------------
__global__ __launch_bounds__(1024) void phase1_kernel(
    const float* __restrict__ root_rvel,   // (NB, T)
    const float* __restrict__ root_vel)    // (NB, T, 2)
{
    __shared__ float sX[T];
    __shared__ float sO[T];
    __shared__ float sInn[T];
    __shared__ float sU[64];
    __shared__ float sM[64];
    __shared__ float sW[4];

    const int n = blockIdx.x;
    const int t = threadIdx.x;
    const int base = n * TP1;

    // --- scan 1: yaw angle r ---
    sX[t] = root_rvel[n * T + t];
    rwr16_scan(t, sX, sO, sInn, sU, sM, sW);

    float r_excl = (t == 0) ? 0.0f : sO[t - 1];
    float r_last = sO[T - 1];

    float ch, sh;
    half_cs(r_excl, ch, sh);
    g_rot[base + t] = make_float2(ch, sh);
    if (t == T - 1) {
        float c2, s2;
        half_cs(r_last, c2, s2);
        g_rot[base + T] = make_float2(c2, s2);
    }

    // --- world-frame velocity: quat sandwich q*(0,vx,0,vz)*conj(q) ----
    float vx = root_vel[(n * T + t) * 2 + 0];
    float vz = root_vel[(n * T + t) * 2 + 1];
    float tx = fA(fM(ch, vx), fM(sh, vz));
    float tz = fS(fM(ch, vz), fM(sh, vx));
    float wx = fA(fM(tx, ch), fM(tz, sh));
    float wz = fS(fM(tz, ch), fM(tx, sh));

    // --- scan 2: integrate wx ---
    __syncthreads();       // r reads done before overwriting sX/sO
    sX[t] = wx;
    rwr16_scan(t, sX, sO, sInn, sU, sM, sW);
    float pxe = (t == 0) ? 0.0f : sO[t - 1];
    float pxl = sO[T - 1];

    // --- scan 3: integrate wz ---
    __syncthreads();
    sX[t] = wz;
    rwr16_scan(t, sX, sO, sInn, sU, sM, sW);
    float pze = (t == 0) ? 0.0f : sO[t - 1];
    float pzl = sO[T - 1];

    g_pos[base + t] = make_float2(pxe, pze);
    if (t == T - 1) g_pos[base + T] = make_float2(pxl, pzl);
}

// ---------------------------------------------------------------------------
// Phase 2: elementwise over (n, t, j) — exact replica of reference fp32 math.
// ---------------------------------------------------------------------------
__global__ __launch_bounds__(256) void phase2_kernel(
    const float* __restrict__ local_pos,   // (NB, TP1, J, 3)
    const float2* __restrict__ local_rot,  // (NB, TP1, J, 6) as float2 triples
    float* __restrict__ out_pos,           // (NB, TP1, J, 3)
    float4* __restrict__ out_rot)          // (NB, TP1, J)
{
    unsigned int i = blockIdx.x * blockDim.x + threadIdx.x;
    if (i >= TOT2) return;

    unsigned int nt = i / J;
    float2 cs = g_rot[nt];
    float2 pp = g_pos[nt];
    float ch = cs.x, sh = cs.y;
    float px = pp.x, pz = pp.y;

    // ---- 6D -> orthonormal matrix (Gram-Schmidt), IEEE div by norm ----
    float2 r01 = local_rot[(size_t)i * 3 + 0];
    float2 r23 = local_rot[(size_t)i * 3 + 1];
    float2 r45 = local_rot[(size_t)i * 3 + 2];
    float a1x = r01.x, a1y = r01.y, a1z = r23.x;
    float a2x = r23.y, a2y = r45.x, a2z = r45.y;

    float n1 = __fsqrt_rn(fA(fA(fM(a1x, a1x), fM(a1y, a1y)), fM(a1z, a1z)));
    float b1x = fD(a1x, n1), b1y = fD(a1y, n1), b1z = fD(a1z, n1);

    float d = fA(fA(fM(b1x, a2x), fM(b1y, a2y)), fM(b1z, a2z));
    float ux = fS(a2x, fM(d, b1x));
    float uy = fS(a2y, fM(d, b1y));
    float uz = fS(a2z, fM(d, b1z));
    float n2 = __fsqrt_rn(fA(fA(fM(ux, ux), fM(uy, uy)), fM(uz, uz)));
    float b2x = fD(ux, n2), b2y = fD(uy, n2), b2z = fD(uz, n2);

    float b3x = fS(fM(b1y, b2z), fM(b1z, b2y));
    float b3y = fS(fM(b1z, b2x), fM(b1x, b2z));
    float b3z = fS(fM(b1x, b2y), fM(b1y, b2x));

    float m00 = b1x, m01 = b1y, m02 = b1z;
    float m10 = b2x, m11 = b2y, m12 = b2z;
    float m20 = b3x, m21 = b3y, m22 = b3z;

    // ---- matrix -> quaternion ----
    float t0 = fA(fA(fA(1.0f, m00), m11), m22);
    float t1 = fS(fS(fA(1.0f, m00), m11), m22);
    float t2 = fS(fA(fS(1.0f, m00), m11), m22);
    float t3 = fA(fS(fS(1.0f, m00), m11), m22);
    float q0 = __fsqrt_rn(fmaxf(t0, 0.0f));
    float q1 = __fsqrt_rn(fmaxf(t1, 0.0f));
    float q2 = __fsqrt_rn(fmaxf(t2, 0.0f));
    float q3 = __fsqrt_rn(fmaxf(t3, 0.0f));

    int   idx  = 0;
    float best = q0;
    if (q1 > best) { best = q1; idx = 1; }
    if (q2 > best) { best = q2; idx = 2; }
    if (q3 > best) { best = q3; idx = 3; }

    float cw, cx, cy, cz;
    if (idx == 0) {
        cw = fM(q0, q0);    cx = fS(m21, m12);  cy = fS(m02, m20);  cz = fS(m10, m01);
    } else if (idx == 1) {
        cw = fS(m21, m12);  cx = fM(q1, q1);    cy = fA(m10, m01);  cz = fA(m02, m20);
    } else if (idx == 2) {
        cw = fS(m02, m20);  cx = fA(m10, m01);  cy = fM(q2, q2);    cz = fA(m21, m12);
    } else {
        cw = fS(m10, m01);  cx = fA(m20, m02);  cy = fA(m21, m12);  cz = fM(q3, q3);
    }
    float den = __fmul_rn(2.0f, fmaxf(best, 0.1f));
    float qw = fD(cw, den), qx = fD(cx, den), qy = fD(cy, den), qz = fD(cz, den);

    // ---- global_rot = standardize(rot * local_q), rot = (ch, 0, sh, 0) ----
    float ow = fS(fM(ch, qw), fM(sh, qy));
    float ox = fA(fM(ch, qx), fM(sh, qz));
    float oy = fA(fM(ch, qy), fM(sh, qw));
    float oz = fS(fM(ch, qz), fM(sh, qx));
    if (ow < 0.0f) { ow = -ow; ox = -ox; oy = -oy; oz = -oz; }

    // ---- global_pos = quat_apply(rot, local_pos) + pos_xz ----
    const float* lp = local_pos + (size_t)i * 3;
    float vx = lp[0], vy = lp[1], vz = lp[2];

    float tx = fA(fM(ch, vx), fM(sh, vz));
    float ty = fM(ch, vy);
    float tz = fS(fM(ch, vz), fM(sh, vx));
    float ox_p = fA(fM(tx, ch), fM(tz, sh));
    float oy_p = fA(fM(fM(sh, vy), sh), fM(ty, ch));  // + sh^2*vy (w-channel term)
    float oz_p = fS(fM(tz, ch), fM(tx, sh));

    float gx = fA(ox_p, px);
    float gy = oy_p;                 // pos_xz y-component is exactly 0
    float gz = fA(oz_p, pz);

    float* op = out_pos + (size_t)i * 3;
    op[0] = gx; op[1] = gy; op[2] = gz;

    out_rot[i] = make_float4(ow, ox, oy, oz);
}

// ---------------------------------------------------------------------------
extern "C" void kernel_launch(void* const* d_in, const int* in_sizes, int n_in,
                              void* d_out, int out_size) {
    const float* root_rvel = (const float*)d_in[0];
    const float* local_pos = (const float*)d_in[1];
    const float* local_rot = (const float*)d_in[2];
    const float* root_vel  = (const float*)d_in[3];

    float*  out_pos = (float*)d_out;
    float4* out_rot = (float4*)((float*)d_out + POS_ELEMS);

    phase1_kernel<<<NB, 1024>>>(root_rvel, root_vel);

    const int threads = 256;
    const int blocks  = (TOT2 + threads - 1) / threads;
    phase2_kernel<<<blocks, threads>>>(local_pos, (const float2*)local_rot,
                                       out_pos, out_rot);
}

// round 11
// speedup vs baseline: 1.2534x; 1.2534x over previous
#include <cuda_runtime.h>
#include <math.h>

// Shapes (fixed):
//   root_rvel : (256, 1024, 1, 1)
//   local_pos : (256, 1025, 24, 3)
//   local_rot : (256, 1025, 24, 6)
//   root_vel  : (256, 1024, 1, 2)
// Output: concat(flatten(global_pos), flatten(global_rot))

#define NB   256
#define T    1024
#define TP1  1025
#define J    24
#define TOT2 (NB * TP1 * J)           // 6,297,600
#define PAIRS (TOT2 / 2)              // 3,148,800
#define POS_ELEMS (NB * TP1 * J * 3)  // 18,892,800

__device__ float2 g_rot[NB * TP1];  // (ch, sh) half-angle quat (w, y)
__device__ float2 g_pos[NB * TP1];  // integrated (px, pz)

// Plain (non-contracted) fp32 ops to match reference's mul/add/sub/div exactly.
__device__ __forceinline__ float fM(float a, float b) { return __fmul_rn(a, b); }
__device__ __forceinline__ float fA(float a, float b) { return __fadd_rn(a, b); }
__device__ __forceinline__ float fS(float a, float b) { return __fsub_rn(a, b); }
__device__ __forceinline__ float fD(float a, float b) { return __fdiv_rn(a, b); }

// _axis_angle_to_quat for aa = (0, r, 0): exact replica of reference arithmetic.
// fp64 trig rounded to fp32 == correctly-rounded == glibc sinf/cosf (CPU ref).
// Single sincos call: shared range reduction, ~0.6x cost of cos+sin.
__device__ __forceinline__ void half_cs(float r, float& ch, float& sh) {
    float r2 = __fmul_rn(r, r);
    float an = __fsqrt_rn(r2);
    float half = __fmul_rn(0.5f, an);
    double sd, cd;
    sincos((double)half, &sd, &cd);
    ch = (float)cd;
    if (an < 1e-6f) {
        float k = __fsub_rn(0.5f, __fdiv_rn(__fmul_rn(an, an), 48.0f));
        sh = __fmul_rn(r, k);
    } else {
        float s32 = (float)sd;
        float k = __fdiv_rn(s32, an);
        sh = __fmul_rn(r, k);
    }
}

// ---------------------------------------------------------------------------
// XLA ReduceWindowRewriter(base_length=16) cumsum order for length 1024:
//   level A: 64 tiles x 16, sequential L->R scan within tile (init 0)
//   totals u[64] -> recursive: level B: 4 tiles x 16, sequential within tile
//     totals w[4]  -> naive sequential scan (4 <= 16), exclusive by shift
//     scan_u[a] = fl(w_excl[a/16] + mB[a])
//   offsets[a] = scan_u[a-1] (exclusive by shift; 0 for a=0)
//   final[i] = fl(offsets[i/16] + innA[i])
// All adds __fadd_rn, exclusive values taken bit-directly (no re-subtraction).
// ---------------------------------------------------------------------------
__device__ __forceinline__ void rwr16_scan(
    int t, const float* __restrict__ x, float* __restrict__ out,
    float* __restrict__ inn, float* __restrict__ u,
    float* __restrict__ m, float* __restrict__ w)
{
    __syncthreads();   // x fully written
    if (t < 64) {
        float acc = 0.0f;
#pragma unroll
        for (int j = 0; j < 16; j++) {
            acc = __fadd_rn(acc, x[t * 16 + j]);
            inn[t * 16 + j] = acc;
        }
        u[t] = acc;
    }
    __syncthreads();
    if (t < 4) {
        float acc = 0.0f;
#pragma unroll
        for (int j = 0; j < 16; j++) {
            acc = __fadd_rn(acc, u[t * 16 + j]);
            m[t * 16 + j] = acc;
        }
        w[t] = acc;
    }
    __syncthreads();
    if (t == 0) {
        float acc = 0.0f;
#pragma unroll
        for (int c = 0; c < 4; c++) {      // exclusive prefix of w, direct bits
            float p = acc;
            acc = __fadd_rn(acc, w[c]);
            w[c] = p;
        }
    }
    __syncthreads();
    {
        int a = t >> 4;                    // tile index at level A
        float off;
        if (a == 0) {
            off = 0.0f;
        } else {
            int b = a - 1;
            off = __fadd_rn(w[b >> 4], m[b]);   // scan_u[a-1]
        }
        out[t] = __fadd_rn(off, inn[t]);
    }
    __syncthreads();   // out readable by neighbors
}

// ---------------------------------------------------------------------------
// Phase 1: per-batch scans (one 1024-thread block per batch).
// ---------------------------------------------------------------------------
__global__ __launch_bounds__(1024) void phase1_kernel(
    const float* __restrict__ root_rvel,   // (NB, T)
    const float* __restrict__ root_vel)    // (NB, T, 2)
{
    __shared__ float sX[T];
    __shared__ float sO[T];
    __shared__ float sInn[T];
    __shared__ float sU[64];
    __shared__ float sM[64];
    __shared__ float sW[4];

    const int n = blockIdx.x;
    const int t = threadIdx.x;
    const int base = n * TP1;

    // --- scan 1: yaw angle r ---
    sX[t] = root_rvel[n * T + t];
    rwr16_scan(t, sX, sO, sInn, sU, sM, sW);

    float r_excl = (t == 0) ? 0.0f : sO[t - 1];
    float r_last = sO[T - 1];

    float ch, sh;
    half_cs(r_excl, ch, sh);
    g_rot[base + t] = make_float2(ch, sh);
    if (t == T - 1) {
        float c2, s2;
        half_cs(r_last, c2, s2);
        g_rot[base + T] = make_float2(c2, s2);
    }

    // --- world-frame velocity: quat sandwich q*(0,vx,0,vz)*conj(q) ----
    float vx = root_vel[(n * T + t) * 2 + 0];
    float vz = root_vel[(n * T + t) * 2 + 1];
    float tx = fA(fM(ch, vx), fM(sh, vz));
    float tz = fS(fM(ch, vz), fM(sh, vx));
    float wx = fA(fM(tx, ch), fM(tz, sh));
    float wz = fS(fM(tz, ch), fM(tx, sh));

    // --- scan 2: integrate wx ---
    __syncthreads();       // r reads done before overwriting sX/sO
    sX[t] = wx;
    rwr16_scan(t, sX, sO, sInn, sU, sM, sW);
    float pxe = (t == 0) ? 0.0f : sO[t - 1];
    float pxl = sO[T - 1];

    // --- scan 3: integrate wz ---
    __syncthreads();
    sX[t] = wz;
    rwr16_scan(t, sX, sO, sInn, sU, sM, sW);
    float pze = (t == 0) ? 0.0f : sO[t - 1];
    float pzl = sO[T - 1];

    g_pos[base + t] = make_float2(pxe, pze);
    if (t == T - 1) g_pos[base + T] = make_float2(pxl, pzl);
}

// ---------------------------------------------------------------------------
// Per-item math — exact replica of reference fp32 evaluation order.
// ---------------------------------------------------------------------------
__device__ __forceinline__ void item_math(
    float ch, float sh, float px, float pz,
    float a1x, float a1y, float a1z, float a2x, float a2y, float a2z,
    float vx, float vy, float vz,
    float& gx, float& gy, float& gz, float4& rot)
{
    // ---- 6D -> orthonormal matrix (Gram-Schmidt), IEEE div by norm ----
    float n1 = __fsqrt_rn(fA(fA(fM(a1x, a1x), fM(a1y, a1y)), fM(a1z, a1z)));
    float b1x = fD(a1x, n1), b1y = fD(a1y, n1), b1z = fD(a1z, n1);

    float d = fA(fA(fM(b1x, a2x), fM(b1y, a2y)), fM(b1z, a2z));
    float ux = fS(a2x, fM(d, b1x));
    float uy = fS(a2y, fM(d, b1y));
    float uz = fS(a2z, fM(d, b1z));
    float n2 = __fsqrt_rn(fA(fA(fM(ux, ux), fM(uy, uy)), fM(uz, uz)));
    float b2x = fD(ux, n2), b2y = fD(uy, n2), b2z = fD(uz, n2);

    float b3x = fS(fM(b1y, b2z), fM(b1z, b2y));
    float b3y = fS(fM(b1z, b2x), fM(b1x, b2z));
    float b3z = fS(fM(b1x, b2y), fM(b1y, b2x));

    float m00 = b1x, m01 = b1y, m02 = b1z;
    float m10 = b2x, m11 = b2y, m12 = b2z;
    float m20 = b3x, m21 = b3y, m22 = b3z;

    // ---- matrix -> quaternion ----
    float t0 = fA(fA(fA(1.0f, m00), m11), m22);
    float t1 = fS(fS(fA(1.0f, m00), m11), m22);
    float t2 = fS(fA(fS(1.0f, m00), m11), m22);
    float t3 = fA(fS(fS(1.0f, m00), m11), m22);
    float q0 = __fsqrt_rn(fmaxf(t0, 0.0f));
    float q1 = __fsqrt_rn(fmaxf(t1, 0.0f));
    float q2 = __fsqrt_rn(fmaxf(t2, 0.0f));
    float q3 = __fsqrt_rn(fmaxf(t3, 0.0f));

    int   idx  = 0;
    float best = q0;
    if (q1 > best) { best = q1; idx = 1; }
    if (q2 > best) { best = q2; idx = 2; }
    if (q3 > best) { best = q3; idx = 3; }

    float cw, cx, cy, cz;
    if (idx == 0) {
        cw = fM(q0, q0);    cx = fS(m21, m12);  cy = fS(m02, m20);  cz = fS(m10, m01);
    } else if (idx == 1) {
        cw = fS(m21, m12);  cx = fM(q1, q1);    cy = fA(m10, m01);  cz = fA(m02, m20);
    } else if (idx == 2) {
        cw = fS(m02, m20);  cx = fA(m10, m01);  cy = fM(q2, q2);    cz = fA(m21, m12);
    } else {
        cw = fS(m10, m01);  cx = fA(m20, m02);  cy = fA(m21, m12);  cz = fM(q3, q3);
    }
    float den = __fmul_rn(2.0f, fmaxf(best, 0.1f));
    float qw = fD(cw, den), qx = fD(cx, den), qy = fD(cy, den), qz = fD(cz, den);

    // ---- global_rot = standardize(rot * local_q), rot = (ch, 0, sh, 0) ----
    float ow = fS(fM(ch, qw), fM(sh, qy));
    float ox = fA(fM(ch, qx), fM(sh, qz));
    float oy = fA(fM(ch, qy), fM(sh, qw));
    float oz = fS(fM(ch, qz), fM(sh, qx));
    if (ow < 0.0f) { ow = -ow; ox = -ox; oy = -oy; oz = -oz; }
    rot = make_float4(ow, ox, oy, oz);

    // ---- global_pos = quat_apply(rot, local_pos) + pos_xz ----
    float tx = fA(fM(ch, vx), fM(sh, vz));
    float ty = fM(ch, vy);
    float tz = fS(fM(ch, vz), fM(sh, vx));
    float ox_p = fA(fM(tx, ch), fM(tz, sh));
    float oy_p = fA(fM(fM(sh, vy), sh), fM(ty, ch));  // + sh^2*vy (w-channel term)
    float oz_p = fS(fM(tz, ch), fM(tx, sh));

    gx = fA(ox_p, px);
    gy = oy_p;                 // pos_xz y-component is exactly 0
    gz = fA(oz_p, pz);
}

// ---------------------------------------------------------------------------
// Phase 2: two items per thread; float4 loads on local_rot, float2 on
// local_pos; float4 stores on out_rot. Pairs (2k, 2k+1) never cross an
// (n,t) row since J = 24 is even.
// ---------------------------------------------------------------------------
__global__ __launch_bounds__(256) void phase2_kernel(
    const float* __restrict__ local_pos,   // (NB, TP1, J, 3)
    const float4* __restrict__ local_rot,  // (NB, TP1, J, 6) as float4s
    float2* __restrict__ out_pos,          // (NB, TP1, J, 3) as float2s
    float4* __restrict__ out_rot)          // (NB, TP1, J)
{
    unsigned int p = blockIdx.x * blockDim.x + threadIdx.x;
    if (p >= PAIRS) return;

    unsigned int i = 2u * p;          // first item of the pair
    unsigned int nt = i / J;

    float2 cs = g_rot[nt];
    float2 pp = g_pos[nt];
    float ch = cs.x, sh = cs.y;
    float px = pp.x, pz = pp.y;

    // rot: 12 floats = 3 float4 (48B, 16B-aligned for even i)
    const float4* lr = local_rot + (size_t)p * 3;
    float4 A = lr[0], B = lr[1], C = lr[2];
    // pos: 6 floats = 3 float2
    const float2* lp = (const float2*)(local_pos) + (size_t)p * 3;
    float2 P0 = lp[0], P1 = lp[1], P2 = lp[2];

    float gx0, gy0, gz0, gx1, gy1, gz1;
    float4 r0, r1;

    item_math(ch, sh, px, pz,
              A.x, A.y, A.z, A.w, B.x, B.y,
              P0.x, P0.y, P1.x,
              gx0, gy0, gz0, r0);
    item_math(ch, sh, px, pz,
              B.z, B.w, C.x, C.y, C.z, C.w,
              P1.y, P2.x, P2.y,
              gx1, gy1, gz1, r1);

    float2* op = out_pos + (size_t)p * 3;
    op[0] = make_float2(gx0, gy0);
    op[1] = make_float2(gz0, gx1);
    op[2] = make_float2(gy1, gz1);

    out_rot[i]     = r0;
    out_rot[i + 1] = r1;
}

// ---------------------------------------------------------------------------
extern "C" void kernel_launch(void* const* d_in, const int* in_sizes, int n_in,
                              void* d_out, int out_size) {
    const float* root_rvel = (const float*)d_in[0];
    const float* local_pos = (const float*)d_in[1];
    const float* local_rot = (const float*)d_in[2];
    const float* root_vel  = (const float*)d_in[3];

    float*  out_pos = (float*)d_out;
    float4* out_rot = (float4*)((float*)d_out + POS_ELEMS);

    phase1_kernel<<<NB, 1024>>>(root_rvel, root_vel);

    const int threads = 256;
    const int blocks  = (PAIRS + threads - 1) / threads;
    phase2_kernel<<<blocks, threads>>>(local_pos, (const float4*)local_rot,
                                       (float2*)out_pos, out_rot);
}